// round 1
// baseline (speedup 1.0000x reference)
#include <cuda_runtime.h>
#include <math.h>

// Problem constants
#define BB 4
#define SS 2048
#define EE 2048
#define HH 16
#define DD 128
#define DH 64   // DD/2

// ---------------------------------------------------------------------------
// Scratch (device globals — no allocation allowed in kernel_launch)
// ---------------------------------------------------------------------------
__device__ float g_q[(size_t)BB * SS * EE];
__device__ float g_k[(size_t)BB * SS * EE];
__device__ float g_v[(size_t)BB * SS * EE];
__device__ float g_attn[(size_t)BB * SS * EE];

// ---------------------------------------------------------------------------
// SGEMM: C[M,N] = A[M,K] @ W[N,K]^T + bias[N]    (both operands K-contiguous)
// BM=BN=128, BK=16, 256 threads, 8x8 microtile.
// ---------------------------------------------------------------------------
#define BM 128
#define BN 128
#define BK 16

__global__ __launch_bounds__(256) void sgemm_bias_kernel(
    const float* __restrict__ A, const float* __restrict__ W,
    const float* __restrict__ bias, float* __restrict__ C,
    int M, int N, int K)
{
    __shared__ float As[BK][BM];
    __shared__ float Bs[BK][BN];

    const int tid = threadIdx.x;
    const int tr = tid >> 4;        // 0..15 -> 8 output rows each
    const int tc = tid & 15;        // 0..15 -> 8 output cols each

    const size_t rowBase = (size_t)blockIdx.y * BM;
    const size_t colBase = (size_t)blockIdx.x * BN;
    const float* Ab = A + rowBase * K;
    const float* Wb = W + colBase * K;

    const int lr = tid >> 1;           // 0..127
    const int lc = (tid & 1) * 8;      // 0 or 8

    float acc[8][8];
#pragma unroll
    for (int i = 0; i < 8; i++)
#pragma unroll
        for (int j = 0; j < 8; j++) acc[i][j] = 0.f;

    for (int k0 = 0; k0 < K; k0 += BK) {
        float4 a0 = *(const float4*)(Ab + (size_t)lr * K + k0 + lc);
        float4 a1 = *(const float4*)(Ab + (size_t)lr * K + k0 + lc + 4);
        float4 b0 = *(const float4*)(Wb + (size_t)lr * K + k0 + lc);
        float4 b1 = *(const float4*)(Wb + (size_t)lr * K + k0 + lc + 4);

        __syncthreads();   // previous compute done before overwriting tiles
        As[lc + 0][lr] = a0.x; As[lc + 1][lr] = a0.y;
        As[lc + 2][lr] = a0.z; As[lc + 3][lr] = a0.w;
        As[lc + 4][lr] = a1.x; As[lc + 5][lr] = a1.y;
        As[lc + 6][lr] = a1.z; As[lc + 7][lr] = a1.w;
        Bs[lc + 0][lr] = b0.x; Bs[lc + 1][lr] = b0.y;
        Bs[lc + 2][lr] = b0.z; Bs[lc + 3][lr] = b0.w;
        Bs[lc + 4][lr] = b1.x; Bs[lc + 5][lr] = b1.y;
        Bs[lc + 6][lr] = b1.z; Bs[lc + 7][lr] = b1.w;
        __syncthreads();

#pragma unroll
        for (int k = 0; k < BK; k++) {
            float ar[8], br[8];
            *(float4*)(ar)     = *(const float4*)&As[k][tr * 8];
            *(float4*)(ar + 4) = *(const float4*)&As[k][tr * 8 + 4];
            *(float4*)(br)     = *(const float4*)&Bs[k][tc * 8];
            *(float4*)(br + 4) = *(const float4*)&Bs[k][tc * 8 + 4];
#pragma unroll
            for (int i = 0; i < 8; i++)
#pragma unroll
                for (int j = 0; j < 8; j++)
                    acc[i][j] += ar[i] * br[j];
        }
    }

    // epilogue with bias
#pragma unroll
    for (int i = 0; i < 8; i++) {
        size_t row = rowBase + tr * 8 + i;
        float* Crow = C + row * N + colBase + tc * 8;
        float4 o0, o1;
        o0.x = acc[i][0] + bias[colBase + tc * 8 + 0];
        o0.y = acc[i][1] + bias[colBase + tc * 8 + 1];
        o0.z = acc[i][2] + bias[colBase + tc * 8 + 2];
        o0.w = acc[i][3] + bias[colBase + tc * 8 + 3];
        o1.x = acc[i][4] + bias[colBase + tc * 8 + 4];
        o1.y = acc[i][5] + bias[colBase + tc * 8 + 5];
        o1.z = acc[i][6] + bias[colBase + tc * 8 + 6];
        o1.w = acc[i][7] + bias[colBase + tc * 8 + 7];
        *(float4*)(Crow)     = o0;
        *(float4*)(Crow + 4) = o1;
    }
}

// ---------------------------------------------------------------------------
// RoPE, in-place on [B,S,H,D]. angles: [2][S][DH] (0=sin, 1=cos).
// If always==0, applies only when *flag != 0 (read on device: graph-safe).
// ---------------------------------------------------------------------------
__global__ __launch_bounds__(256) void rope_kernel(
    float* __restrict__ x, const float* __restrict__ angles,
    const int* __restrict__ flag, int always)
{
    if (!always && *flag == 0) return;
    size_t i = (size_t)blockIdx.x * blockDim.x + threadIdx.x;
    const size_t total = (size_t)BB * SS * HH * DH;
    if (i >= total) return;
    int half = (int)(i % DH);
    int h    = (int)((i / DH) % HH);
    int s    = (int)((i / ((size_t)DH * HH)) % SS);
    int b    = (int)(i / ((size_t)DH * HH * SS));

    float sn = angles[(size_t)s * DH + half];                     // angles[0]
    float cs = angles[(size_t)SS * DH + (size_t)s * DH + half];   // angles[1]

    size_t base = (((size_t)b * SS + s) * HH + h) * (size_t)DD;
    float x1 = x[base + half];
    float x2 = x[base + DH + half];
    x[base + half]      = x1 * cs - x2 * sn;
    x[base + DH + half] = x1 * sn + x2 * cs;
}

// ---------------------------------------------------------------------------
// Flash attention (fp32). One CTA = (b,h, 64 q-rows). 256 threads.
// smem: Qt[128][68], Kt[128][68] (d-major, padded), Vs[64][128], Ps[64][64],
//       km[64] -> 119040 bytes dynamic.
// ---------------------------------------------------------------------------
#define AQ 64
#define AK 64
#define QTP 68   // padded row length for transposed tiles

__global__ __launch_bounds__(256) void attn_kernel(
    const float* __restrict__ q, const float* __restrict__ k,
    const float* __restrict__ v, const int* __restrict__ amask,
    const int* __restrict__ causal_ptr, float* __restrict__ outp)
{
    extern __shared__ float sm[];
    float* Qt = sm;                       // 128*68 = 8704
    float* Kt = sm + 8704;                // 8704
    float* Vs = sm + 17408;               // 64*128 = 8192
    float* Ps = sm + 25600;               // 64*64  = 4096
    int*   km = (int*)(sm + 29696);       // 64

    const int tid = threadIdx.x;
    const int ty = tid >> 4;              // 0..15 -> 4 q rows each
    const int tx = tid & 15;              // 0..15 -> 4 k cols / 8 d cols
    const int bh = blockIdx.x;
    const int b  = bh >> 4;               // HH = 16
    const int h  = bh & 15;
    const int q0 = blockIdx.y * AQ;
    const int causal = *causal_ptr;

    const size_t rowStride = (size_t)HH * DD;   // 2048
    const float* qb = q + ((size_t)b * SS + q0) * rowStride + (size_t)h * DD;

    // Load Q tile transposed: Qt[d][r]
    for (int i = tid; i < AQ * 32; i += 256) {
        int r  = i >> 5;
        int c4 = (i & 31) * 4;
        float4 vq = *(const float4*)(qb + (size_t)r * rowStride + c4);
        Qt[(c4 + 0) * QTP + r] = vq.x;
        Qt[(c4 + 1) * QTP + r] = vq.y;
        Qt[(c4 + 2) * QTP + r] = vq.z;
        Qt[(c4 + 3) * QTP + r] = vq.w;
    }

    float accv[4][8];
#pragma unroll
    for (int i = 0; i < 4; i++)
#pragma unroll
        for (int j = 0; j < 8; j++) accv[i][j] = 0.f;
    float mi[4], li[4];
#pragma unroll
    for (int i = 0; i < 4; i++) { mi[i] = -1e30f; li[i] = 0.f; }

    const float scale = 0.0883883476483184f;   // 1/sqrt(128)

    for (int kt = 0; kt < SS / AK; kt++) {
        __syncthreads();   // previous iteration's PV done with Vs/Ps

        const float* kb = k + ((size_t)b * SS + kt * AK) * rowStride + (size_t)h * DD;
        const float* vb = v + ((size_t)b * SS + kt * AK) * rowStride + (size_t)h * DD;
        for (int i = tid; i < AK * 32; i += 256) {
            int r  = i >> 5;
            int c4 = (i & 31) * 4;
            float4 kv = *(const float4*)(kb + (size_t)r * rowStride + c4);
            Kt[(c4 + 0) * QTP + r] = kv.x;
            Kt[(c4 + 1) * QTP + r] = kv.y;
            Kt[(c4 + 2) * QTP + r] = kv.z;
            Kt[(c4 + 3) * QTP + r] = kv.w;
            float4 vv = *(const float4*)(vb + (size_t)r * rowStride + c4);
            *(float4*)&Vs[r * DD + c4] = vv;
        }
        if (tid < AK) km[tid] = amask[(size_t)b * SS + kt * AK + tid];
        __syncthreads();

        // S = Q @ K^T  (outer product over d)
        float sf[4][4];
#pragma unroll
        for (int i = 0; i < 4; i++)
#pragma unroll
            for (int j = 0; j < 4; j++) sf[i][j] = 0.f;

#pragma unroll 8
        for (int d = 0; d < DD; d++) {
            float4 qv = *(const float4*)&Qt[d * QTP + ty * 4];
            float4 kv = *(const float4*)&Kt[d * QTP + tx * 4];
            sf[0][0] += qv.x * kv.x; sf[0][1] += qv.x * kv.y;
            sf[0][2] += qv.x * kv.z; sf[0][3] += qv.x * kv.w;
            sf[1][0] += qv.y * kv.x; sf[1][1] += qv.y * kv.y;
            sf[1][2] += qv.y * kv.z; sf[1][3] += qv.y * kv.w;
            sf[2][0] += qv.z * kv.x; sf[2][1] += qv.z * kv.y;
            sf[2][2] += qv.z * kv.z; sf[2][3] += qv.z * kv.w;
            sf[3][0] += qv.w * kv.x; sf[3][1] += qv.w * kv.y;
            sf[3][2] += qv.w * kv.z; sf[3][3] += qv.w * kv.w;
        }

        // mask + scale
#pragma unroll
        for (int i = 0; i < 4; i++) {
            int qg = q0 + ty * 4 + i;
#pragma unroll
            for (int j = 0; j < 4; j++) {
                int kg = kt * AK + tx * 4 + j;
                bool ok = (km[tx * 4 + j] != 0) && (!causal || kg <= qg);
                sf[i][j] = ok ? sf[i][j] * scale : -1e30f;
            }
        }

        // online softmax (rows live across the 16 tx lanes of a half-warp)
#pragma unroll
        for (int i = 0; i < 4; i++) {
            float tmax = fmaxf(fmaxf(sf[i][0], sf[i][1]), fmaxf(sf[i][2], sf[i][3]));
#pragma unroll
            for (int o = 8; o > 0; o >>= 1)
                tmax = fmaxf(tmax, __shfl_xor_sync(0xffffffffu, tmax, o));
            float nm = fmaxf(mi[i], tmax);

            float p[4], rs = 0.f;
#pragma unroll
            for (int j = 0; j < 4; j++) {
                p[j] = (sf[i][j] <= -1e29f) ? 0.f : __expf(sf[i][j] - nm);
                rs += p[j];
            }
#pragma unroll
            for (int o = 8; o > 0; o >>= 1)
                rs += __shfl_xor_sync(0xffffffffu, rs, o);

            float alpha = __expf(mi[i] - nm);
            li[i] = li[i] * alpha + rs;
            mi[i] = nm;
#pragma unroll
            for (int jj = 0; jj < 8; jj++) accv[i][jj] *= alpha;

            *(float4*)&Ps[(ty * 4 + i) * AK + tx * 4] = make_float4(p[0], p[1], p[2], p[3]);
        }
        __syncthreads();

        // O += P @ V
#pragma unroll 4
        for (int c = 0; c < AK; c++) {
            float4 v0 = *(const float4*)&Vs[c * DD + tx * 8];
            float4 v1 = *(const float4*)&Vs[c * DD + tx * 8 + 4];
#pragma unroll
            for (int i = 0; i < 4; i++) {
                float pp = Ps[(ty * 4 + i) * AK + c];
                accv[i][0] += pp * v0.x; accv[i][1] += pp * v0.y;
                accv[i][2] += pp * v0.z; accv[i][3] += pp * v0.w;
                accv[i][4] += pp * v1.x; accv[i][5] += pp * v1.y;
                accv[i][6] += pp * v1.z; accv[i][7] += pp * v1.w;
            }
        }
    }

    // normalize + store
    float* ob = outp + ((size_t)b * SS + q0) * rowStride + (size_t)h * DD;
#pragma unroll
    for (int i = 0; i < 4; i++) {
        float inv = (li[i] > 0.f) ? 1.f / li[i] : 0.f;
        int r = ty * 4 + i;
        float4 o0 = make_float4(accv[i][0] * inv, accv[i][1] * inv,
                                accv[i][2] * inv, accv[i][3] * inv);
        float4 o1 = make_float4(accv[i][4] * inv, accv[i][5] * inv,
                                accv[i][6] * inv, accv[i][7] * inv);
        *(float4*)(ob + (size_t)r * rowStride + tx * 8)     = o0;
        *(float4*)(ob + (size_t)r * rowStride + tx * 8 + 4) = o1;
    }
}

// ---------------------------------------------------------------------------
// Launch
// ---------------------------------------------------------------------------
extern "C" void kernel_launch(void* const* d_in, const int* in_sizes, int n_in,
                              void* d_out, int out_size)
{
    const float* x_q    = (const float*)d_in[0];
    const float* x_kv   = (const float*)d_in[1];
    const float* Wq     = (const float*)d_in[2];
    const float* bq     = (const float*)d_in[3];
    const float* Wk     = (const float*)d_in[4];
    const float* bk     = (const float*)d_in[5];
    const float* Wv     = (const float*)d_in[6];
    const float* bv     = (const float*)d_in[7];
    const float* Wo     = (const float*)d_in[8];
    const float* bo     = (const float*)d_in[9];
    const float* angles = (const float*)d_in[10];
    const int*   amask  = (const int*)d_in[11];
    const int*   causal = (const int*)d_in[12];
    const int*   k_rope = (const int*)d_in[13];
    float* out = (float*)d_out;

    float *q, *k, *v, *attn;
    cudaGetSymbolAddress((void**)&q,    g_q);
    cudaGetSymbolAddress((void**)&k,    g_k);
    cudaGetSymbolAddress((void**)&v,    g_v);
    cudaGetSymbolAddress((void**)&attn, g_attn);

    const int M = BB * SS;   // 8192
    const int N = EE;        // 2048
    const int K = EE;        // 2048
    dim3 gGrid(N / BN, M / BM);  // (16, 64)

    sgemm_bias_kernel<<<gGrid, 256>>>(x_q,  Wq, bq, q, M, N, K);
    sgemm_bias_kernel<<<gGrid, 256>>>(x_kv, Wk, bk, k, M, N, K);
    sgemm_bias_kernel<<<gGrid, 256>>>(x_kv, Wv, bv, v, M, N, K);

    size_t ropeTotal = (size_t)BB * SS * HH * DH;
    int ropeBlocks = (int)((ropeTotal + 255) / 256);
    rope_kernel<<<ropeBlocks, 256>>>(q, angles, k_rope, 1);
    rope_kernel<<<ropeBlocks, 256>>>(k, angles, k_rope, 0);

    const int smemBytes = 119040;
    cudaFuncSetAttribute(attn_kernel, cudaFuncAttributeMaxDynamicSharedMemorySize, smemBytes);
    dim3 aGrid(BB * HH, SS / AQ);   // (64, 32)
    attn_kernel<<<aGrid, 256, smemBytes>>>(q, k, v, amask, causal, attn);

    sgemm_bias_kernel<<<gGrid, 256>>>(attn, Wo, bo, out, M, N, K);
}

// round 5
// speedup vs baseline: 1.2450x; 1.2450x over previous
#include <cuda_runtime.h>
#include <cuda_bf16.h>
#include <cstdint>
#include <math.h>

// Problem constants
#define BB 4
#define SS 2048
#define EE 2048
#define HH 16
#define DD 128
#define DH 64   // DD/2

// ---------------------------------------------------------------------------
// Scratch (device globals — no allocation allowed in kernel_launch)
// ---------------------------------------------------------------------------
__device__ float g_q[(size_t)BB * SS * EE];
__device__ float g_k[(size_t)BB * SS * EE];
__device__ float g_v[(size_t)BB * SS * EE];
__device__ float g_attn[(size_t)BB * SS * EE];

// ---------------------------------------------------------------------------
// mma.sync helpers (sm_80-era path; works under plain sm_100 ptxas target)
// ---------------------------------------------------------------------------
__device__ __forceinline__ uint32_t smem_u32(const void* p) {
    uint32_t a;
    asm("{ .reg .u64 t; cvta.to.shared.u64 t, %1; cvt.u32.u64 %0, t; }"
        : "=r"(a) : "l"(p));
    return a;
}

__device__ __forceinline__ void ldsm4(uint32_t* r, uint32_t addr) {
    asm volatile("ldmatrix.sync.aligned.m8n8.x4.shared.b16 {%0,%1,%2,%3}, [%4];"
        : "=r"(r[0]), "=r"(r[1]), "=r"(r[2]), "=r"(r[3]) : "r"(addr));
}

__device__ __forceinline__ void mma_bf16(float* d, const uint32_t* a,
                                         const uint32_t* b) {
    asm volatile(
        "mma.sync.aligned.m16n8k16.row.col.f32.bf16.bf16.f32 "
        "{%0,%1,%2,%3}, {%4,%5,%6,%7}, {%8,%9}, {%0,%1,%2,%3};"
        : "+f"(d[0]), "+f"(d[1]), "+f"(d[2]), "+f"(d[3])
        : "r"(a[0]), "r"(a[1]), "r"(a[2]), "r"(a[3]), "r"(b[0]), "r"(b[1]));
}

// ---------------------------------------------------------------------------
// Split-bf16 tensor-core GEMM: C[M,N] = A[M,K] @ W[N,K]^T + bias[N]
// A = Ahi + Alo (bf16 pair); C ~= Ahi*Bhi + Ahi*Blo + Alo*Bhi  (err ~2^-16)
// CTA 128x128, BK=32, 8 warps (4x2 of 32x64 warp tiles), 256 threads.
// ---------------------------------------------------------------------------
#define GBM 128
#define GBN 128
#define GBK 32
#define LDS 40   // padded k-stride (elements); 80B row stride -> ldmatrix conflict-free

__global__ __launch_bounds__(256) void gemm_bf16s_kernel(
    const float* __restrict__ A, const float* __restrict__ W,
    const float* __restrict__ bias, float* __restrict__ C,
    int M, int N, int K)
{
    __shared__ __nv_bfloat16 sAhi[GBM * LDS];
    __shared__ __nv_bfloat16 sAlo[GBM * LDS];
    __shared__ __nv_bfloat16 sBhi[GBN * LDS];
    __shared__ __nv_bfloat16 sBlo[GBN * LDS];

    const int tid  = threadIdx.x;
    const int lane = tid & 31;
    const int wid  = tid >> 5;
    const int wm   = wid & 3;      // 0..3 -> 32-row band
    const int wn   = wid >> 2;     // 0..1 -> 64-col band
    const size_t m0 = (size_t)blockIdx.y * GBM;
    const size_t n0 = (size_t)blockIdx.x * GBN;

    float acc[2][8][4];
#pragma unroll
    for (int i = 0; i < 2; i++)
#pragma unroll
        for (int j = 0; j < 8; j++)
#pragma unroll
            for (int e = 0; e < 4; e++) acc[i][j][e] = 0.f;

    // global load mapping: thread -> row lr (0..127), 16 consecutive cols
    const int lr  = tid >> 1;
    const int lcb = (tid & 1) * 16;
    const float* Ar = A + (m0 + lr) * (size_t)K + lcb;
    const float* Wr = W + (n0 + lr) * (size_t)K + lcb;

    // ldmatrix lane addressing (within-tile element offsets)
    const int a_row = wm * 32 + (lane & 15);
    const int a_col = (lane >> 4) << 3;
    const int b_row = wn * 64 + ((lane >> 4) << 3) + (lane & 7);
    const int b_col = ((lane >> 3) & 1) << 3;

    const uint32_t uAhi = smem_u32(sAhi), uAlo = smem_u32(sAlo);
    const uint32_t uBhi = smem_u32(sBhi), uBlo = smem_u32(sBlo);

    const int nChunks = K / GBK;
    for (int c = 0; c < nChunks; c++) {
        // stage global loads in registers while smem is still being read
        float4 av[4], wv[4];
        const float* Ac = Ar + c * GBK;
        const float* Wc = Wr + c * GBK;
#pragma unroll
        for (int j = 0; j < 4; j++) {
            av[j] = *(const float4*)(Ac + j * 4);
            wv[j] = *(const float4*)(Wc + j * 4);
        }
        __syncthreads();

        // convert to hi/lo bf16 and store (4-wide packed stores)
#pragma unroll
        for (int j = 0; j < 4; j++) {
            const float* af = (const float*)&av[j];
            const float* wf = (const float*)&wv[j];
            __nv_bfloat16 ah[4], al[4], wh[4], wl[4];
#pragma unroll
            for (int e = 0; e < 4; e++) {
                float x = af[e];
                ah[e] = __float2bfloat16(x);
                al[e] = __float2bfloat16(x - __bfloat162float(ah[e]));
                float y = wf[e];
                wh[e] = __float2bfloat16(y);
                wl[e] = __float2bfloat16(y - __bfloat162float(wh[e]));
            }
            int off = lr * LDS + lcb + j * 4;
            *(uint2*)&sAhi[off] = *(uint2*)ah;
            *(uint2*)&sAlo[off] = *(uint2*)al;
            *(uint2*)&sBhi[off] = *(uint2*)wh;
            *(uint2*)&sBlo[off] = *(uint2*)wl;
        }
        __syncthreads();

        // compute: 2 k-steps of 16
#pragma unroll
        for (int ks = 0; ks < 2; ks++) {
            const int kk = ks * 16;
            uint32_t ahi[2][4], alo[2][4];
#pragma unroll
            for (int mi = 0; mi < 2; mi++) {
                uint32_t aoff = (uint32_t)(((a_row + mi * 16) * LDS + kk + a_col) * 2);
                ldsm4(ahi[mi], uAhi + aoff);
                ldsm4(alo[mi], uAlo + aoff);
            }
#pragma unroll
            for (int nb = 0; nb < 4; nb++) {
                uint32_t boff = (uint32_t)(((b_row + nb * 16) * LDS + kk + b_col) * 2);
                uint32_t bh[4], bl[4];
                ldsm4(bh, uBhi + boff);
                ldsm4(bl, uBlo + boff);
#pragma unroll
                for (int mi = 0; mi < 2; mi++) {
                    mma_bf16(acc[mi][nb * 2 + 0], ahi[mi], bh + 0);
                    mma_bf16(acc[mi][nb * 2 + 1], ahi[mi], bh + 2);
                    mma_bf16(acc[mi][nb * 2 + 0], ahi[mi], bl + 0);
                    mma_bf16(acc[mi][nb * 2 + 1], ahi[mi], bl + 2);
                    mma_bf16(acc[mi][nb * 2 + 0], alo[mi], bh + 0);
                    mma_bf16(acc[mi][nb * 2 + 1], alo[mi], bh + 2);
                }
            }
        }
    }

    // epilogue: d-frag layout -> global with bias
    const int er = lane >> 2;           // 0..7
    const int ec = (lane & 3) * 2;      // 0,2,4,6
#pragma unroll
    for (int mi = 0; mi < 2; mi++) {
#pragma unroll
        for (int nbb = 0; nbb < 8; nbb++) {
            size_t row0 = m0 + wm * 32 + mi * 16 + er;
            size_t col  = n0 + wn * 64 + nbb * 8 + ec;
            float b0 = __ldg(bias + col);
            float b1 = __ldg(bias + col + 1);
            float2 o0 = make_float2(acc[mi][nbb][0] + b0, acc[mi][nbb][1] + b1);
            float2 o1 = make_float2(acc[mi][nbb][2] + b0, acc[mi][nbb][3] + b1);
            *(float2*)(C + row0 * (size_t)N + col)       = o0;
            *(float2*)(C + (row0 + 8) * (size_t)N + col) = o1;
        }
    }
}

// ---------------------------------------------------------------------------
// RoPE, in-place on [B,S,H,D]. angles: [2][S][DH] (0=sin, 1=cos).
// ---------------------------------------------------------------------------
__global__ __launch_bounds__(256) void rope_kernel(
    float* __restrict__ x, const float* __restrict__ angles,
    const int* __restrict__ flag, int always)
{
    if (!always && *flag == 0) return;
    size_t i = (size_t)blockIdx.x * blockDim.x + threadIdx.x;
    const size_t total = (size_t)BB * SS * HH * DH;
    if (i >= total) return;
    int half = (int)(i % DH);
    int h    = (int)((i / DH) % HH);
    int s    = (int)((i / ((size_t)DH * HH)) % SS);
    int b    = (int)(i / ((size_t)DH * HH * SS));

    float sn = angles[(size_t)s * DH + half];
    float cs = angles[(size_t)SS * DH + (size_t)s * DH + half];

    size_t base = (((size_t)b * SS + s) * HH + h) * (size_t)DD;
    float x1 = x[base + half];
    float x2 = x[base + DH + half];
    x[base + half]      = x1 * cs - x2 * sn;
    x[base + DH + half] = x1 * sn + x2 * cs;
}

// ---------------------------------------------------------------------------
// Flash attention (fp32). One CTA = (b,h, 64 q-rows). 256 threads.
// ---------------------------------------------------------------------------
#define AQ 64
#define AK 64
#define QTP 68

__global__ __launch_bounds__(256) void attn_kernel(
    const float* __restrict__ q, const float* __restrict__ k,
    const float* __restrict__ v, const int* __restrict__ amask,
    const int* __restrict__ causal_ptr, float* __restrict__ outp)
{
    extern __shared__ float sm[];
    float* Qt = sm;
    float* Kt = sm + 8704;
    float* Vs = sm + 17408;
    float* Ps = sm + 25600;
    int*   km = (int*)(sm + 29696);

    const int tid = threadIdx.x;
    const int ty = tid >> 4;
    const int tx = tid & 15;
    const int bh = blockIdx.x;
    const int b  = bh >> 4;
    const int h  = bh & 15;
    const int q0 = blockIdx.y * AQ;
    const int causal = *causal_ptr;

    const size_t rowStride = (size_t)HH * DD;
    const float* qb = q + ((size_t)b * SS + q0) * rowStride + (size_t)h * DD;

    for (int i = tid; i < AQ * 32; i += 256) {
        int r  = i >> 5;
        int c4 = (i & 31) * 4;
        float4 vq = *(const float4*)(qb + (size_t)r * rowStride + c4);
        Qt[(c4 + 0) * QTP + r] = vq.x;
        Qt[(c4 + 1) * QTP + r] = vq.y;
        Qt[(c4 + 2) * QTP + r] = vq.z;
        Qt[(c4 + 3) * QTP + r] = vq.w;
    }

    float accv[4][8];
#pragma unroll
    for (int i = 0; i < 4; i++)
#pragma unroll
        for (int j = 0; j < 8; j++) accv[i][j] = 0.f;
    float mi[4], li[4];
#pragma unroll
    for (int i = 0; i < 4; i++) { mi[i] = -1e30f; li[i] = 0.f; }

    const float scale = 0.0883883476483184f;

    for (int kt = 0; kt < SS / AK; kt++) {
        __syncthreads();

        const float* kb = k + ((size_t)b * SS + kt * AK) * rowStride + (size_t)h * DD;
        const float* vb = v + ((size_t)b * SS + kt * AK) * rowStride + (size_t)h * DD;
        for (int i = tid; i < AK * 32; i += 256) {
            int r  = i >> 5;
            int c4 = (i & 31) * 4;
            float4 kv = *(const float4*)(kb + (size_t)r * rowStride + c4);
            Kt[(c4 + 0) * QTP + r] = kv.x;
            Kt[(c4 + 1) * QTP + r] = kv.y;
            Kt[(c4 + 2) * QTP + r] = kv.z;
            Kt[(c4 + 3) * QTP + r] = kv.w;
            float4 vv = *(const float4*)(vb + (size_t)r * rowStride + c4);
            *(float4*)&Vs[r * DD + c4] = vv;
        }
        if (tid < AK) km[tid] = amask[(size_t)b * SS + kt * AK + tid];
        __syncthreads();

        float sf[4][4];
#pragma unroll
        for (int i = 0; i < 4; i++)
#pragma unroll
            for (int j = 0; j < 4; j++) sf[i][j] = 0.f;

#pragma unroll 8
        for (int d = 0; d < DD; d++) {
            float4 qv = *(const float4*)&Qt[d * QTP + ty * 4];
            float4 kv = *(const float4*)&Kt[d * QTP + tx * 4];
            sf[0][0] += qv.x * kv.x; sf[0][1] += qv.x * kv.y;
            sf[0][2] += qv.x * kv.z; sf[0][3] += qv.x * kv.w;
            sf[1][0] += qv.y * kv.x; sf[1][1] += qv.y * kv.y;
            sf[1][2] += qv.y * kv.z; sf[1][3] += qv.y * kv.w;
            sf[2][0] += qv.z * kv.x; sf[2][1] += qv.z * kv.y;
            sf[2][2] += qv.z * kv.z; sf[2][3] += qv.z * kv.w;
            sf[3][0] += qv.w * kv.x; sf[3][1] += qv.w * kv.y;
            sf[3][2] += qv.w * kv.z; sf[3][3] += qv.w * kv.w;
        }

#pragma unroll
        for (int i = 0; i < 4; i++) {
            int qg = q0 + ty * 4 + i;
#pragma unroll
            for (int j = 0; j < 4; j++) {
                int kg = kt * AK + tx * 4 + j;
                bool ok = (km[tx * 4 + j] != 0) && (!causal || kg <= qg);
                sf[i][j] = ok ? sf[i][j] * scale : -1e30f;
            }
        }

#pragma unroll
        for (int i = 0; i < 4; i++) {
            float tmax = fmaxf(fmaxf(sf[i][0], sf[i][1]), fmaxf(sf[i][2], sf[i][3]));
#pragma unroll
            for (int o = 8; o > 0; o >>= 1)
                tmax = fmaxf(tmax, __shfl_xor_sync(0xffffffffu, tmax, o));
            float nm = fmaxf(mi[i], tmax);

            float p[4], rs = 0.f;
#pragma unroll
            for (int j = 0; j < 4; j++) {
                p[j] = (sf[i][j] <= -1e29f) ? 0.f : __expf(sf[i][j] - nm);
                rs += p[j];
            }
#pragma unroll
            for (int o = 8; o > 0; o >>= 1)
                rs += __shfl_xor_sync(0xffffffffu, rs, o);

            float alpha = __expf(mi[i] - nm);
            li[i] = li[i] * alpha + rs;
            mi[i] = nm;
#pragma unroll
            for (int jj = 0; jj < 8; jj++) accv[i][jj] *= alpha;

            *(float4*)&Ps[(ty * 4 + i) * AK + tx * 4] = make_float4(p[0], p[1], p[2], p[3]);
        }
        __syncthreads();

#pragma unroll 4
        for (int c = 0; c < AK; c++) {
            float4 v0 = *(const float4*)&Vs[c * DD + tx * 8];
            float4 v1 = *(const float4*)&Vs[c * DD + tx * 8 + 4];
#pragma unroll
            for (int i = 0; i < 4; i++) {
                float pp = Ps[(ty * 4 + i) * AK + c];
                accv[i][0] += pp * v0.x; accv[i][1] += pp * v0.y;
                accv[i][2] += pp * v0.z; accv[i][3] += pp * v0.w;
                accv[i][4] += pp * v1.x; accv[i][5] += pp * v1.y;
                accv[i][6] += pp * v1.z; accv[i][7] += pp * v1.w;
            }
        }
    }

    float* ob = outp + ((size_t)b * SS + q0) * rowStride + (size_t)h * DD;
#pragma unroll
    for (int i = 0; i < 4; i++) {
        float inv = (li[i] > 0.f) ? 1.f / li[i] : 0.f;
        int r = ty * 4 + i;
        float4 o0 = make_float4(accv[i][0] * inv, accv[i][1] * inv,
                                accv[i][2] * inv, accv[i][3] * inv);
        float4 o1 = make_float4(accv[i][4] * inv, accv[i][5] * inv,
                                accv[i][6] * inv, accv[i][7] * inv);
        *(float4*)(ob + (size_t)r * rowStride + tx * 8)     = o0;
        *(float4*)(ob + (size_t)r * rowStride + tx * 8 + 4) = o1;
    }
}

// ---------------------------------------------------------------------------
// Launch
// ---------------------------------------------------------------------------
extern "C" void kernel_launch(void* const* d_in, const int* in_sizes, int n_in,
                              void* d_out, int out_size)
{
    const float* x_q    = (const float*)d_in[0];
    const float* x_kv   = (const float*)d_in[1];
    const float* Wq     = (const float*)d_in[2];
    const float* bq     = (const float*)d_in[3];
    const float* Wk     = (const float*)d_in[4];
    const float* bk     = (const float*)d_in[5];
    const float* Wv     = (const float*)d_in[6];
    const float* bv     = (const float*)d_in[7];
    const float* Wo     = (const float*)d_in[8];
    const float* bo     = (const float*)d_in[9];
    const float* angles = (const float*)d_in[10];
    const int*   amask  = (const int*)d_in[11];
    const int*   causal = (const int*)d_in[12];
    const int*   k_rope = (const int*)d_in[13];
    float* out = (float*)d_out;

    float *q, *k, *v, *attn;
    cudaGetSymbolAddress((void**)&q,    g_q);
    cudaGetSymbolAddress((void**)&k,    g_k);
    cudaGetSymbolAddress((void**)&v,    g_v);
    cudaGetSymbolAddress((void**)&attn, g_attn);

    const int M = BB * SS;   // 8192
    const int N = EE;        // 2048
    const int K = EE;        // 2048
    dim3 gGrid(N / GBN, M / GBM);   // (16, 64)

    gemm_bf16s_kernel<<<gGrid, 256>>>(x_q,  Wq, bq, q, M, N, K);
    gemm_bf16s_kernel<<<gGrid, 256>>>(x_kv, Wk, bk, k, M, N, K);
    gemm_bf16s_kernel<<<gGrid, 256>>>(x_kv, Wv, bv, v, M, N, K);

    size_t ropeTotal = (size_t)BB * SS * HH * DH;
    int ropeBlocks = (int)((ropeTotal + 255) / 256);
    rope_kernel<<<ropeBlocks, 256>>>(q, angles, k_rope, 1);
    rope_kernel<<<ropeBlocks, 256>>>(k, angles, k_rope, 0);

    const int smemBytes = 119040;
    cudaFuncSetAttribute(attn_kernel, cudaFuncAttributeMaxDynamicSharedMemorySize, smemBytes);
    dim3 aGrid(BB * HH, SS / AQ);   // (64, 32)
    attn_kernel<<<aGrid, 256, smemBytes>>>(q, k, v, amask, causal, attn);

    gemm_bf16s_kernel<<<gGrid, 256>>>(attn, Wo, bo, out, M, N, K);
}

// round 7
// speedup vs baseline: 1.4887x; 1.1957x over previous
#include <cuda_runtime.h>
#include <cuda_bf16.h>
#include <cstdint>
#include <math.h>

// Problem constants
#define BB 4
#define SS 2048
#define EE 2048
#define HH 16
#define DD 128
#define DH 64   // DD/2

#define MM (BB * SS)        // 8192
#define NELEM ((size_t)MM * EE)   // 16,777,216
#define WELEM ((size_t)EE * EE)   // 4,194,304

// ---------------------------------------------------------------------------
// Scratch (device globals — no allocation allowed in kernel_launch)
// ---------------------------------------------------------------------------
__device__ float g_q[NELEM];
__device__ float g_k[NELEM];
__device__ float g_v[NELEM];
__device__ float g_attn[NELEM];

__device__ __nv_bfloat16 g_xq_hi[NELEM],  g_xq_lo[NELEM];
__device__ __nv_bfloat16 g_xkv_hi[NELEM], g_xkv_lo[NELEM];
__device__ __nv_bfloat16 g_at_hi[NELEM],  g_at_lo[NELEM];
__device__ __nv_bfloat16 g_wq_hi[WELEM], g_wq_lo[WELEM];
__device__ __nv_bfloat16 g_wk_hi[WELEM], g_wk_lo[WELEM];
__device__ __nv_bfloat16 g_wv_hi[WELEM], g_wv_lo[WELEM];
__device__ __nv_bfloat16 g_wo_hi[WELEM], g_wo_lo[WELEM];

// ---------------------------------------------------------------------------
// helpers
// ---------------------------------------------------------------------------
__device__ __forceinline__ uint32_t smem_u32(const void* p) {
    uint32_t a;
    asm("{ .reg .u64 t; cvta.to.shared.u64 t, %1; cvt.u32.u64 %0, t; }"
        : "=r"(a) : "l"(p));
    return a;
}

__device__ __forceinline__ void ldsm4(uint32_t* r, uint32_t addr) {
    asm volatile("ldmatrix.sync.aligned.m8n8.x4.shared.b16 {%0,%1,%2,%3}, [%4];"
        : "=r"(r[0]), "=r"(r[1]), "=r"(r[2]), "=r"(r[3]) : "r"(addr));
}

__device__ __forceinline__ void mma_bf16(float* d, const uint32_t* a,
                                         const uint32_t* b) {
    asm volatile(
        "mma.sync.aligned.m16n8k16.row.col.f32.bf16.bf16.f32 "
        "{%0,%1,%2,%3}, {%4,%5,%6,%7}, {%8,%9}, {%0,%1,%2,%3};"
        : "+f"(d[0]), "+f"(d[1]), "+f"(d[2]), "+f"(d[3])
        : "r"(a[0]), "r"(a[1]), "r"(a[2]), "r"(a[3]), "r"(b[0]), "r"(b[1]));
}

__device__ __forceinline__ void cp16(uint32_t dst, const void* src) {
    asm volatile("cp.async.ca.shared.global [%0], [%1], 16;"
        :: "r"(dst), "l"((uint64_t)__cvta_generic_to_global(src)));
}
#define CP_COMMIT() asm volatile("cp.async.commit_group;")
#define CP_WAIT(n)  asm volatile("cp.async.wait_group %0;" :: "n"(n))

// ---------------------------------------------------------------------------
// Split fp32 -> (hi, lo) bf16 pair
// ---------------------------------------------------------------------------
__global__ __launch_bounds__(256) void split_kernel(
    const float* __restrict__ src, __nv_bfloat16* __restrict__ hi,
    __nv_bfloat16* __restrict__ lo, size_t n4)
{
    size_t i = (size_t)blockIdx.x * blockDim.x + threadIdx.x;
    if (i >= n4) return;
    float4 v = *(const float4*)(src + i * 4);
    __nv_bfloat16 h[4], l[4];
    const float* f = (const float*)&v;
#pragma unroll
    for (int e = 0; e < 4; e++) {
        h[e] = __float2bfloat16(f[e]);
        l[e] = __float2bfloat16(f[e] - __bfloat162float(h[e]));
    }
    *(uint2*)(hi + i * 4) = *(uint2*)h;
    *(uint2*)(lo + i * 4) = *(uint2*)l;
}

// ---------------------------------------------------------------------------
// Pre-split bf16 tensor-core GEMM: C = A @ W^T + bias  (3-term split product)
// CTA 128x128, BK=32, cp.async double-buffered, 8 warps.
// dyn smem: 4 matrices x 2 bufs x 128 rows x 40 bf16 = 81920 B
// ---------------------------------------------------------------------------
#define GBM 128
#define GBN 128
#define GBK 32
#define LDS 40
#define BUFB (GBM * LDS * 2)       // 10240 bytes per buffer
#define GEMM_SMEM_BYTES (BUFB * 8)

__global__ __launch_bounds__(256) void gemm_bf16p_kernel(
    const __nv_bfloat16* __restrict__ Ahi, const __nv_bfloat16* __restrict__ Alo,
    const __nv_bfloat16* __restrict__ Bhi, const __nv_bfloat16* __restrict__ Blo,
    const float* __restrict__ bias, float* __restrict__ C,
    int M, int N, int K)
{
    extern __shared__ __align__(16) char dsmem[];
    const uint32_t sb = smem_u32(dsmem);

    const int tid  = threadIdx.x;
    const int lane = tid & 31;
    const int wid  = tid >> 5;
    const int wm   = wid & 3;
    const int wn   = wid >> 2;
    const size_t m0 = (size_t)blockIdx.y * GBM;
    const size_t n0 = (size_t)blockIdx.x * GBN;

    float acc[2][8][4];
#pragma unroll
    for (int i = 0; i < 2; i++)
#pragma unroll
        for (int j = 0; j < 8; j++)
#pragma unroll
            for (int e = 0; e < 4; e++) acc[i][j][e] = 0.f;

    // cp.async mapping: 2 segments of 16B per thread per matrix
    const int seg0 = tid * 2;
    const int r0 = seg0 >> 2,        cs0 = seg0 & 3;
    const int r1 = (seg0 + 1) >> 2,  cs1 = (seg0 + 1) & 3;

    // ldmatrix lane addressing (identical to validated R5 kernel)
    const int a_row = wm * 32 + (lane & 15);
    const int a_col = (lane >> 4) << 3;
    const int b_row = wn * 64 + ((lane >> 4) << 3) + (lane & 7);
    const int b_col = ((lane >> 3) & 1) << 3;

    const int nChunks = K / GBK;

#define PREFETCH(c, s) do {                                                     \
    size_t ca = (size_t)(c) * GBK;                                              \
    uint32_t d0 = (uint32_t)(r0 * 80 + cs0 * 16);                               \
    uint32_t d1 = (uint32_t)(r1 * 80 + cs1 * 16);                               \
    cp16(sb + (0 + (s)) * BUFB + d0, Ahi + (m0 + r0) * K + ca + cs0 * 8);       \
    cp16(sb + (0 + (s)) * BUFB + d1, Ahi + (m0 + r1) * K + ca + cs1 * 8);       \
    cp16(sb + (2 + (s)) * BUFB + d0, Alo + (m0 + r0) * K + ca + cs0 * 8);       \
    cp16(sb + (2 + (s)) * BUFB + d1, Alo + (m0 + r1) * K + ca + cs1 * 8);       \
    cp16(sb + (4 + (s)) * BUFB + d0, Bhi + (n0 + r0) * K + ca + cs0 * 8);       \
    cp16(sb + (4 + (s)) * BUFB + d1, Bhi + (n0 + r1) * K + ca + cs1 * 8);       \
    cp16(sb + (6 + (s)) * BUFB + d0, Blo + (n0 + r0) * K + ca + cs0 * 8);       \
    cp16(sb + (6 + (s)) * BUFB + d1, Blo + (n0 + r1) * K + ca + cs1 * 8);       \
} while (0)

    PREFETCH(0, 0);
    CP_COMMIT();

    for (int c = 0; c < nChunks; c++) {
        const int s = c & 1;
        if (c + 1 < nChunks) {
            PREFETCH(c + 1, s ^ 1);
            CP_COMMIT();
            CP_WAIT(1);
        } else {
            CP_WAIT(0);
        }
        __syncthreads();

        const uint32_t uAhi = sb + (0 + s) * BUFB;
        const uint32_t uAlo = sb + (2 + s) * BUFB;
        const uint32_t uBhi = sb + (4 + s) * BUFB;
        const uint32_t uBlo = sb + (6 + s) * BUFB;

#pragma unroll
        for (int ks = 0; ks < 2; ks++) {
            const int kk = ks * 16;
            uint32_t ahi[2][4], alo[2][4];
#pragma unroll
            for (int mi = 0; mi < 2; mi++) {
                uint32_t aoff = (uint32_t)(((a_row + mi * 16) * LDS + kk + a_col) * 2);
                ldsm4(ahi[mi], uAhi + aoff);
                ldsm4(alo[mi], uAlo + aoff);
            }
#pragma unroll
            for (int nb = 0; nb < 4; nb++) {
                uint32_t boff = (uint32_t)(((b_row + nb * 16) * LDS + kk + b_col) * 2);
                uint32_t bh[4], bl[4];
                ldsm4(bh, uBhi + boff);
                ldsm4(bl, uBlo + boff);
#pragma unroll
                for (int mi = 0; mi < 2; mi++) {
                    mma_bf16(acc[mi][nb * 2 + 0], ahi[mi], bh + 0);
                    mma_bf16(acc[mi][nb * 2 + 1], ahi[mi], bh + 2);
                    mma_bf16(acc[mi][nb * 2 + 0], ahi[mi], bl + 0);
                    mma_bf16(acc[mi][nb * 2 + 1], ahi[mi], bl + 2);
                    mma_bf16(acc[mi][nb * 2 + 0], alo[mi], bh + 0);
                    mma_bf16(acc[mi][nb * 2 + 1], alo[mi], bh + 2);
                }
            }
        }
        __syncthreads();
    }

    // epilogue
    const int er = lane >> 2;
    const int ec = (lane & 3) * 2;
#pragma unroll
    for (int mi = 0; mi < 2; mi++) {
#pragma unroll
        for (int nbb = 0; nbb < 8; nbb++) {
            size_t row0 = m0 + wm * 32 + mi * 16 + er;
            size_t col  = n0 + wn * 64 + nbb * 8 + ec;
            float b0 = __ldg(bias + col);
            float b1 = __ldg(bias + col + 1);
            float2 o0 = make_float2(acc[mi][nbb][0] + b0, acc[mi][nbb][1] + b1);
            float2 o1 = make_float2(acc[mi][nbb][2] + b0, acc[mi][nbb][3] + b1);
            *(float2*)(C + row0 * (size_t)N + col)       = o0;
            *(float2*)(C + (row0 + 8) * (size_t)N + col) = o1;
        }
    }
}

// ---------------------------------------------------------------------------
// RoPE, in-place on [B,S,H,D]. angles: [2][S][DH] (0=sin, 1=cos).
// ---------------------------------------------------------------------------
__global__ __launch_bounds__(256) void rope_kernel(
    float* __restrict__ x, const float* __restrict__ angles,
    const int* __restrict__ flag, int always)
{
    if (!always && *flag == 0) return;
    size_t i = (size_t)blockIdx.x * blockDim.x + threadIdx.x;
    const size_t total = (size_t)BB * SS * HH * DH;
    if (i >= total) return;
    int half = (int)(i % DH);
    int h    = (int)((i / DH) % HH);
    int s    = (int)((i / ((size_t)DH * HH)) % SS);
    int b    = (int)(i / ((size_t)DH * HH * SS));

    float sn = angles[(size_t)s * DH + half];
    float cs = angles[(size_t)SS * DH + (size_t)s * DH + half];

    size_t base = (((size_t)b * SS + s) * HH + h) * (size_t)DD;
    float x1 = x[base + half];
    float x2 = x[base + DH + half];
    x[base + half]      = x1 * cs - x2 * sn;
    x[base + DH + half] = x1 * sn + x2 * cs;
}

// ---------------------------------------------------------------------------
// Flash attention (fp32). One CTA = (b,h, 64 q-rows). 256 threads.
// ---------------------------------------------------------------------------
#define AQ 64
#define AK 64
#define QTP 68

__global__ __launch_bounds__(256) void attn_kernel(
    const float* __restrict__ q, const float* __restrict__ k,
    const float* __restrict__ v, const int* __restrict__ amask,
    const int* __restrict__ causal_ptr, float* __restrict__ outp)
{
    extern __shared__ float sm[];
    float* Qt = sm;
    float* Kt = sm + 8704;
    float* Vs = sm + 17408;
    float* Ps = sm + 25600;
    int*   km = (int*)(sm + 29696);

    const int tid = threadIdx.x;
    const int ty = tid >> 4;
    const int tx = tid & 15;
    const int bh = blockIdx.x;
    const int b  = bh >> 4;
    const int h  = bh & 15;
    const int q0 = blockIdx.y * AQ;
    const int causal = *causal_ptr;

    const size_t rowStride = (size_t)HH * DD;
    const float* qb = q + ((size_t)b * SS + q0) * rowStride + (size_t)h * DD;

    for (int i = tid; i < AQ * 32; i += 256) {
        int r  = i >> 5;
        int c4 = (i & 31) * 4;
        float4 vq = *(const float4*)(qb + (size_t)r * rowStride + c4);
        Qt[(c4 + 0) * QTP + r] = vq.x;
        Qt[(c4 + 1) * QTP + r] = vq.y;
        Qt[(c4 + 2) * QTP + r] = vq.z;
        Qt[(c4 + 3) * QTP + r] = vq.w;
    }

    float accv[4][8];
#pragma unroll
    for (int i = 0; i < 4; i++)
#pragma unroll
        for (int j = 0; j < 8; j++) accv[i][j] = 0.f;
    float mi[4], li[4];
#pragma unroll
    for (int i = 0; i < 4; i++) { mi[i] = -1e30f; li[i] = 0.f; }

    const float scale = 0.0883883476483184f;

    for (int kt = 0; kt < SS / AK; kt++) {
        __syncthreads();

        const float* kb = k + ((size_t)b * SS + kt * AK) * rowStride + (size_t)h * DD;
        const float* vb = v + ((size_t)b * SS + kt * AK) * rowStride + (size_t)h * DD;
        for (int i = tid; i < AK * 32; i += 256) {
            int r  = i >> 5;
            int c4 = (i & 31) * 4;
            float4 kv = *(const float4*)(kb + (size_t)r * rowStride + c4);
            Kt[(c4 + 0) * QTP + r] = kv.x;
            Kt[(c4 + 1) * QTP + r] = kv.y;
            Kt[(c4 + 2) * QTP + r] = kv.z;
            Kt[(c4 + 3) * QTP + r] = kv.w;
            float4 vv = *(const float4*)(vb + (size_t)r * rowStride + c4);
            *(float4*)&Vs[r * DD + c4] = vv;
        }
        if (tid < AK) km[tid] = amask[(size_t)b * SS + kt * AK + tid];
        __syncthreads();

        float sf[4][4];
#pragma unroll
        for (int i = 0; i < 4; i++)
#pragma unroll
            for (int j = 0; j < 4; j++) sf[i][j] = 0.f;

#pragma unroll 8
        for (int d = 0; d < DD; d++) {
            float4 qv = *(const float4*)&Qt[d * QTP + ty * 4];
            float4 kv = *(const float4*)&Kt[d * QTP + tx * 4];
            sf[0][0] += qv.x * kv.x; sf[0][1] += qv.x * kv.y;
            sf[0][2] += qv.x * kv.z; sf[0][3] += qv.x * kv.w;
            sf[1][0] += qv.y * kv.x; sf[1][1] += qv.y * kv.y;
            sf[1][2] += qv.y * kv.z; sf[1][3] += qv.y * kv.w;
            sf[2][0] += qv.z * kv.x; sf[2][1] += qv.z * kv.y;
            sf[2][2] += qv.z * kv.z; sf[2][3] += qv.z * kv.w;
            sf[3][0] += qv.w * kv.x; sf[3][1] += qv.w * kv.y;
            sf[3][2] += qv.w * kv.z; sf[3][3] += qv.w * kv.w;
        }

#pragma unroll
        for (int i = 0; i < 4; i++) {
            int qg = q0 + ty * 4 + i;
#pragma unroll
            for (int j = 0; j < 4; j++) {
                int kg = kt * AK + tx * 4 + j;
                bool ok = (km[tx * 4 + j] != 0) && (!causal || kg <= qg);
                sf[i][j] = ok ? sf[i][j] * scale : -1e30f;
            }
        }

#pragma unroll
        for (int i = 0; i < 4; i++) {
            float tmax = fmaxf(fmaxf(sf[i][0], sf[i][1]), fmaxf(sf[i][2], sf[i][3]));
#pragma unroll
            for (int o = 8; o > 0; o >>= 1)
                tmax = fmaxf(tmax, __shfl_xor_sync(0xffffffffu, tmax, o));
            float nm = fmaxf(mi[i], tmax);

            float p[4], rs = 0.f;
#pragma unroll
            for (int j = 0; j < 4; j++) {
                p[j] = (sf[i][j] <= -1e29f) ? 0.f : __expf(sf[i][j] - nm);
                rs += p[j];
            }
#pragma unroll
            for (int o = 8; o > 0; o >>= 1)
                rs += __shfl_xor_sync(0xffffffffu, rs, o);

            float alpha = __expf(mi[i] - nm);
            li[i] = li[i] * alpha + rs;
            mi[i] = nm;
#pragma unroll
            for (int jj = 0; jj < 8; jj++) accv[i][jj] *= alpha;

            *(float4*)&Ps[(ty * 4 + i) * AK + tx * 4] = make_float4(p[0], p[1], p[2], p[3]);
        }
        __syncthreads();

#pragma unroll 4
        for (int c = 0; c < AK; c++) {
            float4 v0 = *(const float4*)&Vs[c * DD + tx * 8];
            float4 v1 = *(const float4*)&Vs[c * DD + tx * 8 + 4];
#pragma unroll
            for (int i = 0; i < 4; i++) {
                float pp = Ps[(ty * 4 + i) * AK + c];
                accv[i][0] += pp * v0.x; accv[i][1] += pp * v0.y;
                accv[i][2] += pp * v0.z; accv[i][3] += pp * v0.w;
                accv[i][4] += pp * v1.x; accv[i][5] += pp * v1.y;
                accv[i][6] += pp * v1.z; accv[i][7] += pp * v1.w;
            }
        }
    }

    float* ob = outp + ((size_t)b * SS + q0) * rowStride + (size_t)h * DD;
#pragma unroll
    for (int i = 0; i < 4; i++) {
        float inv = (li[i] > 0.f) ? 1.f / li[i] : 0.f;
        int r = ty * 4 + i;
        float4 o0 = make_float4(accv[i][0] * inv, accv[i][1] * inv,
                                accv[i][2] * inv, accv[i][3] * inv);
        float4 o1 = make_float4(accv[i][4] * inv, accv[i][5] * inv,
                                accv[i][6] * inv, accv[i][7] * inv);
        *(float4*)(ob + (size_t)r * rowStride + tx * 8)     = o0;
        *(float4*)(ob + (size_t)r * rowStride + tx * 8 + 4) = o1;
    }
}

// ---------------------------------------------------------------------------
// Launch
// ---------------------------------------------------------------------------
extern "C" void kernel_launch(void* const* d_in, const int* in_sizes, int n_in,
                              void* d_out, int out_size)
{
    const float* x_q    = (const float*)d_in[0];
    const float* x_kv   = (const float*)d_in[1];
    const float* Wq     = (const float*)d_in[2];
    const float* bq     = (const float*)d_in[3];
    const float* Wk     = (const float*)d_in[4];
    const float* bk     = (const float*)d_in[5];
    const float* Wv     = (const float*)d_in[6];
    const float* bv     = (const float*)d_in[7];
    const float* Wo     = (const float*)d_in[8];
    const float* bo     = (const float*)d_in[9];
    const float* angles = (const float*)d_in[10];
    const int*   amask  = (const int*)d_in[11];
    const int*   causal = (const int*)d_in[12];
    const int*   k_rope = (const int*)d_in[13];
    float* out = (float*)d_out;

    float *q, *k, *v, *attn;
    cudaGetSymbolAddress((void**)&q,    g_q);
    cudaGetSymbolAddress((void**)&k,    g_k);
    cudaGetSymbolAddress((void**)&v,    g_v);
    cudaGetSymbolAddress((void**)&attn, g_attn);

    __nv_bfloat16 *xq_hi, *xq_lo, *xkv_hi, *xkv_lo, *at_hi, *at_lo;
    __nv_bfloat16 *wq_hi, *wq_lo, *wk_hi, *wk_lo, *wv_hi, *wv_lo, *wo_hi, *wo_lo;
    cudaGetSymbolAddress((void**)&xq_hi,  g_xq_hi);
    cudaGetSymbolAddress((void**)&xq_lo,  g_xq_lo);
    cudaGetSymbolAddress((void**)&xkv_hi, g_xkv_hi);
    cudaGetSymbolAddress((void**)&xkv_lo, g_xkv_lo);
    cudaGetSymbolAddress((void**)&at_hi,  g_at_hi);
    cudaGetSymbolAddress((void**)&at_lo,  g_at_lo);
    cudaGetSymbolAddress((void**)&wq_hi,  g_wq_hi);
    cudaGetSymbolAddress((void**)&wq_lo,  g_wq_lo);
    cudaGetSymbolAddress((void**)&wk_hi,  g_wk_hi);
    cudaGetSymbolAddress((void**)&wk_lo,  g_wk_lo);
    cudaGetSymbolAddress((void**)&wv_hi,  g_wv_hi);
    cudaGetSymbolAddress((void**)&wv_lo,  g_wv_lo);
    cudaGetSymbolAddress((void**)&wo_hi,  g_wo_hi);
    cudaGetSymbolAddress((void**)&wo_lo,  g_wo_lo);

    const int M = MM;        // 8192
    const int N = EE;        // 2048
    const int K = EE;        // 2048

    // splits
    const int xBlocks = (int)(NELEM / 4 / 256);
    const int wBlocks = (int)(WELEM / 4 / 256);
    split_kernel<<<xBlocks, 256>>>(x_q,  xq_hi,  xq_lo,  NELEM / 4);
    split_kernel<<<xBlocks, 256>>>(x_kv, xkv_hi, xkv_lo, NELEM / 4);
    split_kernel<<<wBlocks, 256>>>(Wq, wq_hi, wq_lo, WELEM / 4);
    split_kernel<<<wBlocks, 256>>>(Wk, wk_hi, wk_lo, WELEM / 4);
    split_kernel<<<wBlocks, 256>>>(Wv, wv_hi, wv_lo, WELEM / 4);
    split_kernel<<<wBlocks, 256>>>(Wo, wo_hi, wo_lo, WELEM / 4);

    cudaFuncSetAttribute(gemm_bf16p_kernel,
                         cudaFuncAttributeMaxDynamicSharedMemorySize, GEMM_SMEM_BYTES);
    dim3 gGrid(N / GBN, M / GBM);   // (16, 64)

    gemm_bf16p_kernel<<<gGrid, 256, GEMM_SMEM_BYTES>>>(xq_hi,  xq_lo,  wq_hi, wq_lo, bq, q, M, N, K);
    gemm_bf16p_kernel<<<gGrid, 256, GEMM_SMEM_BYTES>>>(xkv_hi, xkv_lo, wk_hi, wk_lo, bk, k, M, N, K);
    gemm_bf16p_kernel<<<gGrid, 256, GEMM_SMEM_BYTES>>>(xkv_hi, xkv_lo, wv_hi, wv_lo, bv, v, M, N, K);

    size_t ropeTotal = (size_t)BB * SS * HH * DH;
    int ropeBlocks = (int)((ropeTotal + 255) / 256);
    rope_kernel<<<ropeBlocks, 256>>>(q, angles, k_rope, 1);
    rope_kernel<<<ropeBlocks, 256>>>(k, angles, k_rope, 0);

    const int smemBytes = 119040;
    cudaFuncSetAttribute(attn_kernel, cudaFuncAttributeMaxDynamicSharedMemorySize, smemBytes);
    dim3 aGrid(BB * HH, SS / AQ);   // (64, 32)
    attn_kernel<<<aGrid, 256, smemBytes>>>(q, k, v, amask, causal, attn);

    split_kernel<<<xBlocks, 256>>>(attn, at_hi, at_lo, NELEM / 4);
    gemm_bf16p_kernel<<<gGrid, 256, GEMM_SMEM_BYTES>>>(at_hi, at_lo, wo_hi, wo_lo, bo, out, M, N, K);
}